// round 1
// baseline (speedup 1.0000x reference)
#include <cuda_runtime.h>

#define HIDN  4096
#define NBATCH 2
#define SEQL  2048
#define NHEAD 32
#define NKVH  8
#define DHEAD 128
#define NTOK  (NBATCH * SEQL)

// Scratch (allocation-free rule: __device__ globals)
__device__ float g_Q[(size_t)NBATCH * NHEAD * SEQL * DHEAD];   // [b,h,s,d]
__device__ float g_K[(size_t)NBATCH * NKVH  * SEQL * DHEAD];   // [b,kv,s,d]
__device__ float g_V[(size_t)NBATCH * NKVH  * SEQL * DHEAD];   // [b,kv,s,d]
__device__ float g_A[(size_t)NTOK * HIDN];                     // [t, h*D+d]

// ---------------------------------------------------------------------------
// NT SGEMM: C[t,o] = sum_k A[t,k] * W[o,k] + bias[o]
// A: [4096, K] row-major, W: [N, K] row-major (both K-contiguous).
// mode 0: scatter into [b, head, s, d] layout (nheads heads of 128)
// mode 1: plain row-major [t, N]
// ---------------------------------------------------------------------------
__global__ __launch_bounds__(256)
void sgemm_nt(const float* __restrict__ A, const float* __restrict__ W,
              const float* __restrict__ bias, float* __restrict__ C,
              int K, int N, int mode, int nheads)
{
    __shared__ __align__(16) float As[16][132];
    __shared__ __align__(16) float Bs[16][132];

    const int tid = threadIdx.x;
    const int tx = tid & 15;
    const int ty = tid >> 4;
    const int m0 = blockIdx.y * 128;
    const int n0 = blockIdx.x * 128;

    const int lrow = tid >> 2;        // 0..63
    const int lk   = (tid & 3) << 2;  // 0,4,8,12

    const float* Ag = A + (size_t)m0 * K;
    const float* Wg = W + (size_t)n0 * K;

    float acc[8][8];
#pragma unroll
    for (int i = 0; i < 8; i++)
#pragma unroll
        for (int j = 0; j < 8; j++) acc[i][j] = 0.0f;

    for (int k0 = 0; k0 < K; k0 += 16) {
        float4 a0 = *(const float4*)(Ag + (size_t)lrow        * K + k0 + lk);
        float4 a1 = *(const float4*)(Ag + (size_t)(lrow + 64) * K + k0 + lk);
        float4 b0 = *(const float4*)(Wg + (size_t)lrow        * K + k0 + lk);
        float4 b1 = *(const float4*)(Wg + (size_t)(lrow + 64) * K + k0 + lk);

        __syncthreads();
        As[lk + 0][lrow] = a0.x;  As[lk + 1][lrow] = a0.y;
        As[lk + 2][lrow] = a0.z;  As[lk + 3][lrow] = a0.w;
        As[lk + 0][lrow + 64] = a1.x;  As[lk + 1][lrow + 64] = a1.y;
        As[lk + 2][lrow + 64] = a1.z;  As[lk + 3][lrow + 64] = a1.w;
        Bs[lk + 0][lrow] = b0.x;  Bs[lk + 1][lrow] = b0.y;
        Bs[lk + 2][lrow] = b0.z;  Bs[lk + 3][lrow] = b0.w;
        Bs[lk + 0][lrow + 64] = b1.x;  Bs[lk + 1][lrow + 64] = b1.y;
        Bs[lk + 2][lrow + 64] = b1.z;  Bs[lk + 3][lrow + 64] = b1.w;
        __syncthreads();

#pragma unroll
        for (int kk = 0; kk < 16; kk++) {
            float ra[8], rb[8];
            *(float4*)&ra[0] = *(const float4*)&As[kk][ty * 8];
            *(float4*)&ra[4] = *(const float4*)&As[kk][ty * 8 + 4];
            *(float4*)&rb[0] = *(const float4*)&Bs[kk][tx * 8];
            *(float4*)&rb[4] = *(const float4*)&Bs[kk][tx * 8 + 4];
#pragma unroll
            for (int i = 0; i < 8; i++)
#pragma unroll
                for (int j = 0; j < 8; j++)
                    acc[i][j] += ra[i] * rb[j];
        }
    }

    // Epilogue
#pragma unroll
    for (int i = 0; i < 8; i++) {
        const int t = m0 + ty * 8 + i;
#pragma unroll
        for (int jj = 0; jj < 8; jj += 4) {
            const int o = n0 + tx * 8 + jj;
            float4 r;
            r.x = acc[i][jj + 0] + bias[o + 0];
            r.y = acc[i][jj + 1] + bias[o + 1];
            r.z = acc[i][jj + 2] + bias[o + 2];
            r.w = acc[i][jj + 3] + bias[o + 3];
            size_t idx;
            if (mode == 0) {
                const int b = t >> 11, s = t & 2047;
                const int h = o >> 7, d = o & 127;
                idx = (((size_t)(b * nheads + h)) * SEQL + s) * DHEAD + d;
            } else {
                idx = (size_t)t * N + o;
            }
            *(float4*)&C[idx] = r;
        }
    }
}

// ---------------------------------------------------------------------------
// Causal flash attention, GQA (q head h -> kv head h % 8 per reference concat)
// Block: 256 threads = (tx 0..15, ty 0..15).  Q tile 64 rows, KV tile 64.
// smem: QT [128][68] (transposed+swizzled), KT/V union [8704 f], Pt [64][68].
// ---------------------------------------------------------------------------
__global__ __launch_bounds__(256)
void flash_attn(const float* __restrict__ Qg, const float* __restrict__ Kg,
                const float* __restrict__ Vg, float* __restrict__ Out)
{
    extern __shared__ __align__(16) float sm[];
    float* smq  = sm;                   // 128*68 = 8704
    float* smkv = sm + 128 * 68;        // 8704 (KT: [128][68], V: [64][132])
    float* smp  = sm + 2 * 128 * 68;    // 64*68 = 4352

    const int tid = threadIdx.x;
    const int tx = tid & 15;
    const int ty = tid >> 4;
    const int qi = blockIdx.x;   // q tile (64 rows)
    const int h  = blockIdx.y;
    const int b  = blockIdx.z;
    const int kvh = h & 7;
    const float scale = 0.08838834764831845f;  // 1/sqrt(128)

    // Load Q tile transposed into smq[d][m] (swizzled), pre-scaled
    {
        const float4* Qp = (const float4*)(Qg +
            (((size_t)(b * NHEAD + h)) * SEQL + (size_t)qi * 64) * DHEAD);
#pragma unroll
        for (int it = 0; it < 8; it++) {
            const int lin = it * 256 + tid;
            const int m = lin >> 5, d4 = lin & 31;
            float4 v = Qp[(size_t)m * 32 + d4];
            const int d = d4 << 2;
            const int base = ((((m >> 2) ^ (d4 & 15)) << 2) | (m & 3));
            smq[(d + 0) * 68 + base] = v.x * scale;
            smq[(d + 1) * 68 + base] = v.y * scale;
            smq[(d + 2) * 68 + base] = v.z * scale;
            smq[(d + 3) * 68 + base] = v.w * scale;
        }
    }

    float acc[4][8];
#pragma unroll
    for (int i = 0; i < 4; i++)
#pragma unroll
        for (int j = 0; j < 8; j++) acc[i][j] = 0.0f;
    float mrow[4], lrow[4];
#pragma unroll
    for (int i = 0; i < 4; i++) { mrow[i] = -1e30f; lrow[i] = 0.0f; }

    const size_t kvbase = (((size_t)(b * NKVH + kvh)) * SEQL) * DHEAD;

    for (int j = 0; j <= qi; j++) {
        __syncthreads();  // previous iteration's PV reads done

        // Load K tile transposed into smkv[d][n] (swizzled)
        {
            const float4* Kp = (const float4*)(Kg + kvbase + (size_t)j * 64 * DHEAD);
#pragma unroll
            for (int it = 0; it < 8; it++) {
                const int lin = it * 256 + tid;
                const int n = lin >> 5, d4 = lin & 31;
                float4 v = Kp[(size_t)n * 32 + d4];
                const int d = d4 << 2;
                const int base = ((((n >> 2) ^ (d4 & 15)) << 2) | (n & 3));
                smkv[(d + 0) * 68 + base] = v.x;
                smkv[(d + 1) * 68 + base] = v.y;
                smkv[(d + 2) * 68 + base] = v.z;
                smkv[(d + 3) * 68 + base] = v.w;
            }
        }
        __syncthreads();

        // Scores: s[i][jj] = sum_d Q[m][d]*K[n][d], m=ty*4+i, n=tx*4+jj
        float s[4][4];
#pragma unroll
        for (int i = 0; i < 4; i++)
#pragma unroll
            for (int jj = 0; jj < 4; jj++) s[i][jj] = 0.0f;

#pragma unroll 4
        for (int d = 0; d < 128; d++) {
            const int blk = (d >> 2) & 15;
            const float4 qv = *(const float4*)&smq [d * 68 + ((ty ^ blk) << 2)];
            const float4 kv = *(const float4*)&smkv[d * 68 + ((tx ^ blk) << 2)];
            s[0][0] += qv.x * kv.x;  s[0][1] += qv.x * kv.y;
            s[0][2] += qv.x * kv.z;  s[0][3] += qv.x * kv.w;
            s[1][0] += qv.y * kv.x;  s[1][1] += qv.y * kv.y;
            s[1][2] += qv.y * kv.z;  s[1][3] += qv.y * kv.w;
            s[2][0] += qv.z * kv.x;  s[2][1] += qv.z * kv.y;
            s[2][2] += qv.z * kv.z;  s[2][3] += qv.z * kv.w;
            s[3][0] += qv.w * kv.x;  s[3][1] += qv.w * kv.y;
            s[3][2] += qv.w * kv.z;  s[3][3] += qv.w * kv.w;
        }

        // Causal mask on diagonal tile
        if (j == qi) {
#pragma unroll
            for (int i = 0; i < 4; i++)
#pragma unroll
                for (int jj = 0; jj < 4; jj++)
                    if (tx * 4 + jj > ty * 4 + i) s[i][jj] = -1e30f;
        }

        // Online softmax (row groups of 16 lanes: lanes with same ty)
#pragma unroll
        for (int i = 0; i < 4; i++) {
            float tm = fmaxf(fmaxf(s[i][0], s[i][1]), fmaxf(s[i][2], s[i][3]));
            tm = fmaxf(tm, __shfl_xor_sync(0xffffffffu, tm, 1));
            tm = fmaxf(tm, __shfl_xor_sync(0xffffffffu, tm, 2));
            tm = fmaxf(tm, __shfl_xor_sync(0xffffffffu, tm, 4));
            tm = fmaxf(tm, __shfl_xor_sync(0xffffffffu, tm, 8));
            const float mn = fmaxf(mrow[i], tm);
            const float corr = __expf(mrow[i] - mn);
            mrow[i] = mn;
            float ps = 0.0f;
#pragma unroll
            for (int jj = 0; jj < 4; jj++) {
                const float p = __expf(s[i][jj] - mn);
                ps += p;
                smp[(tx * 4 + jj) * 68 + (((ty ^ tx) << 2) | i)] = p;
            }
            ps += __shfl_xor_sync(0xffffffffu, ps, 1);
            ps += __shfl_xor_sync(0xffffffffu, ps, 2);
            ps += __shfl_xor_sync(0xffffffffu, ps, 4);
            ps += __shfl_xor_sync(0xffffffffu, ps, 8);
            lrow[i] = lrow[i] * corr + ps;
#pragma unroll
            for (int jj = 0; jj < 8; jj++) acc[i][jj] *= corr;
        }
        __syncthreads();  // done reading KT & writing Pt

        // Load V tile (row-major) into the KT buffer
        {
            const float4* Vp = (const float4*)(Vg + kvbase + (size_t)j * 64 * DHEAD);
#pragma unroll
            for (int it = 0; it < 8; it++) {
                const int lin = it * 256 + tid;
                const int n = lin >> 5, d4 = lin & 31;
                *(float4*)&smkv[n * 132 + (d4 << 2)] = Vp[(size_t)n * 32 + d4];
            }
        }
        __syncthreads();

        // PV: acc[i][jj] += P[m][n] * V[n][d],  d = tx*8+jj
#pragma unroll 4
        for (int n = 0; n < 64; n++) {
            const float4 pv = *(const float4*)&smp[n * 68 + ((ty ^ (n >> 2)) << 2)];
            const float4 v0 = *(const float4*)&smkv[n * 132 + tx * 8];
            const float4 v1 = *(const float4*)&smkv[n * 132 + tx * 8 + 4];
            acc[0][0] += pv.x * v0.x;  acc[0][1] += pv.x * v0.y;
            acc[0][2] += pv.x * v0.z;  acc[0][3] += pv.x * v0.w;
            acc[0][4] += pv.x * v1.x;  acc[0][5] += pv.x * v1.y;
            acc[0][6] += pv.x * v1.z;  acc[0][7] += pv.x * v1.w;
            acc[1][0] += pv.y * v0.x;  acc[1][1] += pv.y * v0.y;
            acc[1][2] += pv.y * v0.z;  acc[1][3] += pv.y * v0.w;
            acc[1][4] += pv.y * v1.x;  acc[1][5] += pv.y * v1.y;
            acc[1][6] += pv.y * v1.z;  acc[1][7] += pv.y * v1.w;
            acc[2][0] += pv.z * v0.x;  acc[2][1] += pv.z * v0.y;
            acc[2][2] += pv.z * v0.z;  acc[2][3] += pv.z * v0.w;
            acc[2][4] += pv.z * v1.x;  acc[2][5] += pv.z * v1.y;
            acc[2][6] += pv.z * v1.z;  acc[2][7] += pv.z * v1.w;
            acc[3][0] += pv.w * v0.x;  acc[3][1] += pv.w * v0.y;
            acc[3][2] += pv.w * v0.z;  acc[3][3] += pv.w * v0.w;
            acc[3][4] += pv.w * v1.x;  acc[3][5] += pv.w * v1.y;
            acc[3][6] += pv.w * v1.z;  acc[3][7] += pv.w * v1.w;
        }
    }

    // Normalize and write [t, h*128 + d]
#pragma unroll
    for (int i = 0; i < 4; i++) {
        const float inv = 1.0f / lrow[i];
        const int t = b * SEQL + qi * 64 + ty * 4 + i;
        float* dst = Out + (size_t)t * HIDN + h * DHEAD + tx * 8;
        float4 o0, o1;
        o0.x = acc[i][0] * inv;  o0.y = acc[i][1] * inv;
        o0.z = acc[i][2] * inv;  o0.w = acc[i][3] * inv;
        o1.x = acc[i][4] * inv;  o1.y = acc[i][5] * inv;
        o1.z = acc[i][6] * inv;  o1.w = acc[i][7] * inv;
        *(float4*)&dst[0] = o0;
        *(float4*)&dst[4] = o1;
    }
}

// ---------------------------------------------------------------------------
extern "C" void kernel_launch(void* const* d_in, const int* in_sizes, int n_in,
                              void* d_out, int out_size)
{
    const float* x   = (const float*)d_in[0];
    // d_in[1] = mask: causal structure applied analytically, not read.
    const float* q_w = (const float*)d_in[2];
    const float* q_b = (const float*)d_in[3];
    const float* k_w = (const float*)d_in[4];
    const float* k_b = (const float*)d_in[5];
    const float* v_w = (const float*)d_in[6];
    const float* v_b = (const float*)d_in[7];
    const float* o_w = (const float*)d_in[8];
    const float* o_b = (const float*)d_in[9];
    float* out = (float*)d_out;

    float *qp, *kp, *vp, *ap;
    cudaGetSymbolAddress((void**)&qp, g_Q);
    cudaGetSymbolAddress((void**)&kp, g_K);
    cudaGetSymbolAddress((void**)&vp, g_V);
    cudaGetSymbolAddress((void**)&ap, g_A);

    const int smem_bytes = (2 * 128 * 68 + 64 * 68) * (int)sizeof(float);  // 87040
    cudaFuncSetAttribute(flash_attn, cudaFuncAttributeMaxDynamicSharedMemorySize,
                         smem_bytes);

    dim3 blk(256);
    // Projections
    sgemm_nt<<<dim3(32, 32), blk>>>(x, q_w, q_b, qp, HIDN, HIDN, 0, NHEAD);
    sgemm_nt<<<dim3(8,  32), blk>>>(x, k_w, k_b, kp, HIDN, NKVH * DHEAD, 0, NKVH);
    sgemm_nt<<<dim3(8,  32), blk>>>(x, v_w, v_b, vp, HIDN, NKVH * DHEAD, 0, NKVH);
    // Attention
    flash_attn<<<dim3(SEQL / 64, NHEAD, NBATCH), blk, smem_bytes>>>(qp, kp, vp, ap);
    // Output projection
    sgemm_nt<<<dim3(32, 32), blk>>>(ap, o_w, o_b, out, HIDN, HIDN, 1, 0);
}

// round 3
// speedup vs baseline: 2.0080x; 2.0080x over previous
#include <cuda_runtime.h>
#include <cuda_fp16.h>
#include <cstdint>

#define HIDN  4096
#define NBATCH 2
#define SEQL  2048
#define NHEAD 32
#define NKVH  8
#define DHEAD 128
#define NTOK  (NBATCH * SEQL)
#define KDIM  4096

// ---------------------------------------------------------------------------
// Device scratch (allocation-free rule)
// ---------------------------------------------------------------------------
__device__ float  g_Q[(size_t)NBATCH * NHEAD * SEQL * DHEAD];   // [b,h,s,d] fp32
__device__ float  g_K[(size_t)NBATCH * NKVH  * SEQL * DHEAD];
__device__ float  g_V[(size_t)NBATCH * NKVH  * SEQL * DHEAD];
__device__ float  g_A[(size_t)NTOK * HIDN];                     // attn out fp32

__device__ __half g_Xhi[(size_t)NTOK * KDIM];
__device__ __half g_Xlo[(size_t)NTOK * KDIM];
__device__ __half g_Wqh[(size_t)HIDN * KDIM];
__device__ __half g_Wql[(size_t)HIDN * KDIM];
__device__ __half g_Wkh[(size_t)NKVH * DHEAD * KDIM];
__device__ __half g_Wkl[(size_t)NKVH * DHEAD * KDIM];
__device__ __half g_Wvh[(size_t)NKVH * DHEAD * KDIM];
__device__ __half g_Wvl[(size_t)NKVH * DHEAD * KDIM];
__device__ __half g_Woh[(size_t)HIDN * KDIM];
__device__ __half g_Wol[(size_t)HIDN * KDIM];
__device__ __half g_Ahi[(size_t)NTOK * KDIM];
__device__ __half g_Alo[(size_t)NTOK * KDIM];

// ---------------------------------------------------------------------------
// PTX helpers (all sm_80-era, safe at compute_103)
// ---------------------------------------------------------------------------
__device__ __forceinline__ uint32_t smem_u32(const void* p) {
    uint32_t r;
    asm("{ .reg .u64 t; cvta.to.shared.u64 t, %1; cvt.u32.u64 %0, t; }"
        : "=r"(r) : "l"(p));
    return r;
}

#define CP16(dst, src) \
    asm volatile("cp.async.cg.shared.global [%0], [%1], 16;" \
                 :: "r"(dst), "l"(src) : "memory")
#define CP_COMMIT() asm volatile("cp.async.commit_group;" ::: "memory")
#define CP_WAIT(n)  asm volatile("cp.async.wait_group %0;" :: "n"(n) : "memory")

__device__ __forceinline__ void ldsm4(uint32_t& r0, uint32_t& r1,
                                      uint32_t& r2, uint32_t& r3, uint32_t a) {
    asm volatile("ldmatrix.sync.aligned.m8n8.x4.shared.b16 {%0,%1,%2,%3}, [%4];"
                 : "=r"(r0), "=r"(r1), "=r"(r2), "=r"(r3) : "r"(a));
}

__device__ __forceinline__ void mma16816(float* c, const uint32_t* a,
                                         uint32_t b0, uint32_t b1) {
    asm volatile(
        "mma.sync.aligned.m16n8k16.row.col.f32.f16.f16.f32 "
        "{%0,%1,%2,%3}, {%4,%5,%6,%7}, {%8,%9}, {%0,%1,%2,%3};"
        : "+f"(c[0]), "+f"(c[1]), "+f"(c[2]), "+f"(c[3])
        : "r"(a[0]), "r"(a[1]), "r"(a[2]), "r"(a[3]), "r"(b0), "r"(b1));
}

// ---------------------------------------------------------------------------
// Elementwise fp32 -> fp16 hi/lo split (with scale)
// ---------------------------------------------------------------------------
__global__ void split_f32(const float* __restrict__ in, __half* __restrict__ hi,
                          __half* __restrict__ lo, int n4, float scale)
{
    const int stride = gridDim.x * blockDim.x;
    for (int i = blockIdx.x * blockDim.x + threadIdx.x; i < n4; i += stride) {
        float4 v = ((const float4*)in)[i];
        v.x *= scale; v.y *= scale; v.z *= scale; v.w *= scale;
        __half hx = __float2half_rn(v.x), hy = __float2half_rn(v.y);
        __half hz = __float2half_rn(v.z), hw = __float2half_rn(v.w);
        __half lx = __float2half_rn(v.x - __half2float(hx));
        __half ly = __float2half_rn(v.y - __half2float(hy));
        __half lz = __float2half_rn(v.z - __half2float(hz));
        __half lw = __float2half_rn(v.w - __half2float(hw));
        __half2 h01 = __halves2half2(hx, hy), h23 = __halves2half2(hz, hw);
        __half2 l01 = __halves2half2(lx, ly), l23 = __halves2half2(lz, lw);
        uint2 hp, lp;
        hp.x = *(uint32_t*)&h01; hp.y = *(uint32_t*)&h23;
        lp.x = *(uint32_t*)&l01; lp.y = *(uint32_t*)&l23;
        ((uint2*)hi)[i] = hp;
        ((uint2*)lo)[i] = lp;
    }
}

// ---------------------------------------------------------------------------
// HMMA split-3 NT GEMM: C[t,o] = A[t,:] . W[o,:] * outscale + bias[o]
// A,W given as fp16 hi/lo [rows][4096]. CTA tile 128x128, KC=64, 2-stage
// cp.async pipeline. 8 warps, warp tile 64x32.
// mode 0: scatter into [b, head, s, d]; mode 1: row-major [t, N].
// ---------------------------------------------------------------------------
#define TSZ   16384                 // one 128x64 fp16 tile
#define STAGE (4 * TSZ)             // Ahi, Alo, Bhi, Blo
#define GSMEM (2 * STAGE)           // 131072

__global__ __launch_bounds__(256, 1)
void gemm_hmma(const __half* __restrict__ Ahi, const __half* __restrict__ Alo,
               const __half* __restrict__ Bhi, const __half* __restrict__ Blo,
               const float* __restrict__ bias, float* __restrict__ C,
               int N, int mode, int nheads, float outscale)
{
    extern __shared__ __align__(1024) char sm[];
    const int tid  = threadIdx.x;
    const int wid  = tid >> 5;
    const int lane = tid & 31;
    const int m0 = blockIdx.y * 128;
    const int n0 = blockIdx.x * 128;
    const int wm = (wid >> 2) * 64;      // warp M offset within CTA
    const int wn = (wid & 3) * 32;       // warp N offset within CTA
    const uint32_t sbase = smem_u32(sm);

    const __half* Ah = Ahi + (size_t)m0 * KDIM;
    const __half* Al = Alo + (size_t)m0 * KDIM;
    const __half* Bh = Bhi + (size_t)n0 * KDIM;
    const __half* Bl = Blo + (size_t)n0 * KDIM;

    float acc[4][4][4];
#pragma unroll
    for (int i = 0; i < 4; i++)
#pragma unroll
        for (int j = 0; j < 4; j++)
#pragma unroll
            for (int k = 0; k < 4; k++) acc[i][j][k] = 0.0f;

    // ---- stage loader: 4 tensors x 1024 16B-chunks, xor-swizzled ----
    auto load_stage = [&](int s, int k0) {
        const uint32_t base = sbase + s * STAGE;
#pragma unroll
        for (int i = 0; i < 4; i++) {
            const int idx = tid + i * 256;
            const int r = idx >> 3, c = idx & 7;
            const uint32_t dst = r * 128 + (((uint32_t)(c ^ (r & 7))) << 4);
            const size_t src = (size_t)r * KDIM + k0 + c * 8;
            CP16(base + 0 * TSZ + dst, (const char*)(Ah + src));
            CP16(base + 1 * TSZ + dst, (const char*)(Al + src));
            CP16(base + 2 * TSZ + dst, (const char*)(Bh + src));
            CP16(base + 3 * TSZ + dst, (const char*)(Bl + src));
        }
        CP_COMMIT();
    };

    load_stage(0, 0);

    const int NIT = KDIM / 64;
    for (int it = 0; it < NIT; ++it) {
        if (it + 1 < NIT) load_stage((it + 1) & 1, (it + 1) * 64);
        if (it + 1 < NIT) { CP_WAIT(1); } else { CP_WAIT(0); }
        __syncthreads();

        const uint32_t stg = sbase + (it & 1) * STAGE;
        const uint32_t sAh = stg, sAl = stg + TSZ;
        const uint32_t sBh = stg + 2 * TSZ, sBl = stg + 3 * TSZ;

        uint32_t bh[4][4], bl[4][4];
#pragma unroll
        for (int k16 = 0; k16 < 4; ++k16) {
            if ((k16 & 1) == 0) {
                // load B frags for k16 and k16+1 (x4 spans k32)
#pragma unroll
                for (int nt = 0; nt < 4; ++nt) {
                    const int r = wn + nt * 8 + (lane & 7);
                    const int c = k16 * 2 + (lane >> 3);      // 4 chunks
                    const uint32_t off = r * 128 + (((uint32_t)(c ^ (r & 7))) << 4);
                    ldsm4(bh[nt][0], bh[nt][1], bh[nt][2], bh[nt][3], sBh + off);
                    ldsm4(bl[nt][0], bl[nt][1], bl[nt][2], bl[nt][3], sBl + off);
                }
            }
            const int bo = (k16 & 1) * 2;

            uint32_t ah[4][4], al[4][4];
#pragma unroll
            for (int mt = 0; mt < 4; ++mt) {
                const int r = wm + mt * 16 + (lane & 15);
                const int c = k16 * 2 + (lane >> 4);
                const uint32_t off = r * 128 + (((uint32_t)(c ^ (r & 7))) << 4);
                ldsm4(ah[mt][0], ah[mt][1], ah[mt][2], ah[mt][3], sAh + off);
                ldsm4(al[mt][0], al[mt][1], al[mt][2], al[mt][3], sAl + off);
            }
#pragma unroll
            for (int mt = 0; mt < 4; ++mt)
#pragma unroll
                for (int nt = 0; nt < 4; ++nt) {
                    mma16816(acc[mt][nt], ah[mt], bh[nt][bo], bh[nt][bo + 1]);
                    mma16816(acc[mt][nt], ah[mt], bl[nt][bo], bl[nt][bo + 1]);
                    mma16816(acc[mt][nt], al[mt], bh[nt][bo], bh[nt][bo + 1]);
                }
        }
        __syncthreads();
    }

    // ---- epilogue ----
#pragma unroll
    for (int mt = 0; mt < 4; ++mt) {
#pragma unroll
        for (int nt = 0; nt < 4; ++nt) {
            const int o = n0 + wn + nt * 8 + 2 * (lane & 3);
            const float b0 = bias[o], b1 = bias[o + 1];
#pragma unroll
            for (int half = 0; half < 2; ++half) {
                const int t = m0 + wm + mt * 16 + (lane >> 2) + half * 8;
                float2 v;
                v.x = acc[mt][nt][half * 2 + 0] * outscale + b0;
                v.y = acc[mt][nt][half * 2 + 1] * outscale + b1;
                size_t idx;
                if (mode == 0) {
                    const int bb = t >> 11, s = t & 2047;
                    const int h = o >> 7, d = o & 127;
                    idx = (((size_t)(bb * nheads + h)) * SEQL + s) * DHEAD + d;
                } else {
                    idx = (size_t)t * N + o;
                }
                *(float2*)&C[idx] = v;
            }
        }
    }
}

// ---------------------------------------------------------------------------
// Causal flash attention, fp32 (validated in R1, unchanged)
// ---------------------------------------------------------------------------
__global__ __launch_bounds__(256)
void flash_attn(const float* __restrict__ Qg, const float* __restrict__ Kg,
                const float* __restrict__ Vg, float* __restrict__ Out)
{
    extern __shared__ __align__(16) float smf[];
    float* smq  = smf;
    float* smkv = smf + 128 * 68;
    float* smp  = smf + 2 * 128 * 68;

    const int tid = threadIdx.x;
    const int tx = tid & 15;
    const int ty = tid >> 4;
    const int qi = blockIdx.x;
    const int h  = blockIdx.y;
    const int b  = blockIdx.z;
    const int kvh = h & 7;
    const float scale = 0.08838834764831845f;

    {
        const float4* Qp = (const float4*)(Qg +
            (((size_t)(b * NHEAD + h)) * SEQL + (size_t)qi * 64) * DHEAD);
#pragma unroll
        for (int it = 0; it < 8; it++) {
            const int lin = it * 256 + tid;
            const int m = lin >> 5, d4 = lin & 31;
            float4 v = Qp[(size_t)m * 32 + d4];
            const int d = d4 << 2;
            const int base = ((((m >> 2) ^ (d4 & 15)) << 2) | (m & 3));
            smq[(d + 0) * 68 + base] = v.x * scale;
            smq[(d + 1) * 68 + base] = v.y * scale;
            smq[(d + 2) * 68 + base] = v.z * scale;
            smq[(d + 3) * 68 + base] = v.w * scale;
        }
    }

    float acc[4][8];
#pragma unroll
    for (int i = 0; i < 4; i++)
#pragma unroll
        for (int j = 0; j < 8; j++) acc[i][j] = 0.0f;
    float mrow[4], lrow[4];
#pragma unroll
    for (int i = 0; i < 4; i++) { mrow[i] = -1e30f; lrow[i] = 0.0f; }

    const size_t kvbase = (((size_t)(b * NKVH + kvh)) * SEQL) * DHEAD;

    for (int j = 0; j <= qi; j++) {
        __syncthreads();
        {
            const float4* Kp = (const float4*)(Kg + kvbase + (size_t)j * 64 * DHEAD);
#pragma unroll
            for (int it = 0; it < 8; it++) {
                const int lin = it * 256 + tid;
                const int n = lin >> 5, d4 = lin & 31;
                float4 v = Kp[(size_t)n * 32 + d4];
                const int d = d4 << 2;
                const int base = ((((n >> 2) ^ (d4 & 15)) << 2) | (n & 3));
                smkv[(d + 0) * 68 + base] = v.x;
                smkv[(d + 1) * 68 + base] = v.y;
                smkv[(d + 2) * 68 + base] = v.z;
                smkv[(d + 3) * 68 + base] = v.w;
            }
        }
        __syncthreads();

        float s[4][4];
#pragma unroll
        for (int i = 0; i < 4; i++)
#pragma unroll
            for (int jj = 0; jj < 4; jj++) s[i][jj] = 0.0f;

#pragma unroll 4
        for (int d = 0; d < 128; d++) {
            const int blk = (d >> 2) & 15;
            const float4 qv = *(const float4*)&smq [d * 68 + ((ty ^ blk) << 2)];
            const float4 kv = *(const float4*)&smkv[d * 68 + ((tx ^ blk) << 2)];
            s[0][0] += qv.x * kv.x;  s[0][1] += qv.x * kv.y;
            s[0][2] += qv.x * kv.z;  s[0][3] += qv.x * kv.w;
            s[1][0] += qv.y * kv.x;  s[1][1] += qv.y * kv.y;
            s[1][2] += qv.y * kv.z;  s[1][3] += qv.y * kv.w;
            s[2][0] += qv.z * kv.x;  s[2][1] += qv.z * kv.y;
            s[2][2] += qv.z * kv.z;  s[2][3] += qv.z * kv.w;
            s[3][0] += qv.w * kv.x;  s[3][1] += qv.w * kv.y;
            s[3][2] += qv.w * kv.z;  s[3][3] += qv.w * kv.w;
        }

        if (j == qi) {
#pragma unroll
            for (int i = 0; i < 4; i++)
#pragma unroll
                for (int jj = 0; jj < 4; jj++)
                    if (tx * 4 + jj > ty * 4 + i) s[i][jj] = -1e30f;
        }

#pragma unroll
        for (int i = 0; i < 4; i++) {
            float tm = fmaxf(fmaxf(s[i][0], s[i][1]), fmaxf(s[i][2], s[i][3]));
            tm = fmaxf(tm, __shfl_xor_sync(0xffffffffu, tm, 1));
            tm = fmaxf(tm, __shfl_xor_sync(0xffffffffu, tm, 2));
            tm = fmaxf(tm, __shfl_xor_sync(0xffffffffu, tm, 4));
            tm = fmaxf(tm, __shfl_xor_sync(0xffffffffu, tm, 8));
            const float mn = fmaxf(mrow[i], tm);
            const float corr = __expf(mrow[i] - mn);
            mrow[i] = mn;
            float ps = 0.0f;
#pragma unroll
            for (int jj = 0; jj < 4; jj++) {
                const float p = __expf(s[i][jj] - mn);
                ps += p;
                smp[(tx * 4 + jj) * 68 + (((ty ^ tx) << 2) | i)] = p;
            }
            ps += __shfl_xor_sync(0xffffffffu, ps, 1);
            ps += __shfl_xor_sync(0xffffffffu, ps, 2);
            ps += __shfl_xor_sync(0xffffffffu, ps, 4);
            ps += __shfl_xor_sync(0xffffffffu, ps, 8);
            lrow[i] = lrow[i] * corr + ps;
#pragma unroll
            for (int jj = 0; jj < 8; jj++) acc[i][jj] *= corr;
        }
        __syncthreads();

        {
            const float4* Vp = (const float4*)(Vg + kvbase + (size_t)j * 64 * DHEAD);
#pragma unroll
            for (int it = 0; it < 8; it++) {
                const int lin = it * 256 + tid;
                const int n = lin >> 5, d4 = lin & 31;
                *(float4*)&smkv[n * 132 + (d4 << 2)] = Vp[(size_t)n * 32 + d4];
            }
        }
        __syncthreads();

#pragma unroll 4
        for (int n = 0; n < 64; n++) {
            const float4 pv = *(const float4*)&smp[n * 68 + ((ty ^ (n >> 2)) << 2)];
            const float4 v0 = *(const float4*)&smkv[n * 132 + tx * 8];
            const float4 v1 = *(const float4*)&smkv[n * 132 + tx * 8 + 4];
            acc[0][0] += pv.x * v0.x;  acc[0][1] += pv.x * v0.y;
            acc[0][2] += pv.x * v0.z;  acc[0][3] += pv.x * v0.w;
            acc[0][4] += pv.x * v1.x;  acc[0][5] += pv.x * v1.y;
            acc[0][6] += pv.x * v1.z;  acc[0][7] += pv.x * v1.w;
            acc[1][0] += pv.y * v0.x;  acc[1][1] += pv.y * v0.y;
            acc[1][2] += pv.y * v0.z;  acc[1][3] += pv.y * v0.w;
            acc[1][4] += pv.y * v1.x;  acc[1][5] += pv.y * v1.y;
            acc[1][6] += pv.y * v1.z;  acc[1][7] += pv.y * v1.w;
            acc[2][0] += pv.z * v0.x;  acc[2][1] += pv.z * v0.y;
            acc[2][2] += pv.z * v0.z;  acc[2][3] += pv.z * v0.w;
            acc[2][4] += pv.z * v1.x;  acc[2][5] += pv.z * v1.y;
            acc[2][6] += pv.z * v1.z;  acc[2][7] += pv.z * v1.w;
            acc[3][0] += pv.w * v0.x;  acc[3][1] += pv.w * v0.y;
            acc[3][2] += pv.w * v0.z;  acc[3][3] += pv.w * v0.w;
            acc[3][4] += pv.w * v1.x;  acc[3][5] += pv.w * v1.y;
            acc[3][6] += pv.w * v1.z;  acc[3][7] += pv.w * v1.w;
        }
    }

#pragma unroll
    for (int i = 0; i < 4; i++) {
        const float inv = 1.0f / lrow[i];
        const int t = b * SEQL + qi * 64 + ty * 4 + i;
        float* dst = Out + (size_t)t * HIDN + h * DHEAD + tx * 8;
        float4 o0, o1;
        o0.x = acc[i][0] * inv;  o0.y = acc[i][1] * inv;
        o0.z = acc[i][2] * inv;  o0.w = acc[i][3] * inv;
        o1.x = acc[i][4] * inv;  o1.y = acc[i][5] * inv;
        o1.z = acc[i][6] * inv;  o1.w = acc[i][7] * inv;
        *(float4*)&dst[0] = o0;
        *(float4*)&dst[4] = o1;
    }
}

// ---------------------------------------------------------------------------
extern "C" void kernel_launch(void* const* d_in, const int* in_sizes, int n_in,
                              void* d_out, int out_size)
{
    const float* x   = (const float*)d_in[0];
    // d_in[1] = mask: causal structure applied analytically, not read.
    const float* q_w = (const float*)d_in[2];
    const float* q_b = (const float*)d_in[3];
    const float* k_w = (const float*)d_in[4];
    const float* k_b = (const float*)d_in[5];
    const float* v_w = (const float*)d_in[6];
    const float* v_b = (const float*)d_in[7];
    const float* o_w = (const float*)d_in[8];
    const float* o_b = (const float*)d_in[9];
    float* out = (float*)d_out;

    float *qp, *kp, *vp, *ap;
    cudaGetSymbolAddress((void**)&qp, g_Q);
    cudaGetSymbolAddress((void**)&kp, g_K);
    cudaGetSymbolAddress((void**)&vp, g_V);
    cudaGetSymbolAddress((void**)&ap, g_A);
    __half *xh, *xl, *wqh, *wql, *wkh, *wkl, *wvh, *wvl, *woh, *wol, *ah, *al;
    cudaGetSymbolAddress((void**)&xh, g_Xhi);   cudaGetSymbolAddress((void**)&xl, g_Xlo);
    cudaGetSymbolAddress((void**)&wqh, g_Wqh);  cudaGetSymbolAddress((void**)&wql, g_Wql);
    cudaGetSymbolAddress((void**)&wkh, g_Wkh);  cudaGetSymbolAddress((void**)&wkl, g_Wkl);
    cudaGetSymbolAddress((void**)&wvh, g_Wvh);  cudaGetSymbolAddress((void**)&wvl, g_Wvl);
    cudaGetSymbolAddress((void**)&woh, g_Woh);  cudaGetSymbolAddress((void**)&wol, g_Wol);
    cudaGetSymbolAddress((void**)&ah, g_Ahi);   cudaGetSymbolAddress((void**)&al, g_Alo);

    cudaFuncSetAttribute(gemm_hmma, cudaFuncAttributeMaxDynamicSharedMemorySize,
                         GSMEM);
    const int fa_smem = (2 * 128 * 68 + 64 * 68) * (int)sizeof(float);  // 87040
    cudaFuncSetAttribute(flash_attn, cudaFuncAttributeMaxDynamicSharedMemorySize,
                         fa_smem);

    const float WS = 1024.0f, IWS = 1.0f / 1024.0f;
    dim3 blk(256);

    // Split inputs + weights into fp16 hi/lo
    split_f32<<<1024, 256>>>(x,   xh,  xl,  (NTOK * KDIM) / 4,        1.0f);
    split_f32<<<1024, 256>>>(q_w, wqh, wql, (HIDN * KDIM) / 4,        WS);
    split_f32<<<512,  256>>>(k_w, wkh, wkl, (NKVH * DHEAD * KDIM) / 4, WS);
    split_f32<<<512,  256>>>(v_w, wvh, wvl, (NKVH * DHEAD * KDIM) / 4, WS);
    split_f32<<<1024, 256>>>(o_w, woh, wol, (HIDN * KDIM) / 4,        WS);

    // Projections (HMMA split-3)
    gemm_hmma<<<dim3(32, 32), blk, GSMEM>>>(xh, xl, wqh, wql, q_b, qp,
                                            HIDN, 0, NHEAD, IWS);
    gemm_hmma<<<dim3(8, 32),  blk, GSMEM>>>(xh, xl, wkh, wkl, k_b, kp,
                                            NKVH * DHEAD, 0, NKVH, IWS);
    gemm_hmma<<<dim3(8, 32),  blk, GSMEM>>>(xh, xl, wvh, wvl, v_b, vp,
                                            NKVH * DHEAD, 0, NKVH, IWS);

    // Attention (fp32)
    flash_attn<<<dim3(SEQL / 64, NHEAD, NBATCH), blk, fa_smem>>>(qp, kp, vp, ap);

    // Output projection
    split_f32<<<1024, 256>>>(ap, ah, al, (NTOK * KDIM) / 4, 1.0f);
    gemm_hmma<<<dim3(32, 32), blk, GSMEM>>>(ah, al, woh, wol, o_b, out,
                                            HIDN, 1, 0, IWS);
}

// round 4
// speedup vs baseline: 3.2195x; 1.6033x over previous
#include <cuda_runtime.h>
#include <cuda_fp16.h>
#include <cstdint>

#define HIDN  4096
#define NBATCH 2
#define SEQL  2048
#define NHEAD 32
#define NKVH  8
#define DHEAD 128
#define NTOK  (NBATCH * SEQL)
#define KDIM  4096

// ---------------------------------------------------------------------------
// Device scratch (allocation-free rule)
// ---------------------------------------------------------------------------
__device__ __half g_Xhi[(size_t)NTOK * KDIM];
__device__ __half g_Xlo[(size_t)NTOK * KDIM];
__device__ __half g_Wqh[(size_t)HIDN * KDIM];
__device__ __half g_Wql[(size_t)HIDN * KDIM];
__device__ __half g_Wkh[(size_t)NKVH * DHEAD * KDIM];
__device__ __half g_Wkl[(size_t)NKVH * DHEAD * KDIM];
__device__ __half g_Wvh[(size_t)NKVH * DHEAD * KDIM];
__device__ __half g_Wvl[(size_t)NKVH * DHEAD * KDIM];
__device__ __half g_Woh[(size_t)HIDN * KDIM];
__device__ __half g_Wol[(size_t)HIDN * KDIM];
// QKV in [b, head, s, d], split hi/lo
__device__ __half g_Qh[(size_t)NBATCH * NHEAD * SEQL * DHEAD];
__device__ __half g_Ql[(size_t)NBATCH * NHEAD * SEQL * DHEAD];
__device__ __half g_Kh2[(size_t)NBATCH * NKVH * SEQL * DHEAD];
__device__ __half g_Kl2[(size_t)NBATCH * NKVH * SEQL * DHEAD];
__device__ __half g_Vh2[(size_t)NBATCH * NKVH * SEQL * DHEAD];
__device__ __half g_Vl2[(size_t)NBATCH * NKVH * SEQL * DHEAD];
// attention output [t, hid], split hi/lo (o-proj input)
__device__ __half g_Ahi[(size_t)NTOK * KDIM];
__device__ __half g_Alo[(size_t)NTOK * KDIM];

// ---------------------------------------------------------------------------
// PTX helpers (sm_80-era, safe at compute_103)
// ---------------------------------------------------------------------------
__device__ __forceinline__ uint32_t smem_u32(const void* p) {
    uint32_t r;
    asm("{ .reg .u64 t; cvta.to.shared.u64 t, %1; cvt.u32.u64 %0, t; }"
        : "=r"(r) : "l"(p));
    return r;
}

#define CP16(dst, src) \
    asm volatile("cp.async.cg.shared.global [%0], [%1], 16;" \
                 :: "r"(dst), "l"(src) : "memory")
#define CP_COMMIT() asm volatile("cp.async.commit_group;" ::: "memory")
#define CP_WAIT(n)  asm volatile("cp.async.wait_group %0;" :: "n"(n) : "memory")

__device__ __forceinline__ void ldsm4(uint32_t& r0, uint32_t& r1,
                                      uint32_t& r2, uint32_t& r3, uint32_t a) {
    asm volatile("ldmatrix.sync.aligned.m8n8.x4.shared.b16 {%0,%1,%2,%3}, [%4];"
                 : "=r"(r0), "=r"(r1), "=r"(r2), "=r"(r3) : "r"(a));
}
__device__ __forceinline__ void ldsm4t(uint32_t& r0, uint32_t& r1,
                                       uint32_t& r2, uint32_t& r3, uint32_t a) {
    asm volatile("ldmatrix.sync.aligned.m8n8.x4.trans.shared.b16 {%0,%1,%2,%3}, [%4];"
                 : "=r"(r0), "=r"(r1), "=r"(r2), "=r"(r3) : "r"(a));
}

__device__ __forceinline__ void mma16816(float* c, const uint32_t* a,
                                         uint32_t b0, uint32_t b1) {
    asm volatile(
        "mma.sync.aligned.m16n8k16.row.col.f32.f16.f16.f32 "
        "{%0,%1,%2,%3}, {%4,%5,%6,%7}, {%8,%9}, {%0,%1,%2,%3};"
        : "+f"(c[0]), "+f"(c[1]), "+f"(c[2]), "+f"(c[3])
        : "r"(a[0]), "r"(a[1]), "r"(a[2]), "r"(a[3]), "r"(b0), "r"(b1));
}

// ---------------------------------------------------------------------------
// fp32 -> fp16 hi/lo split (with scale)
// ---------------------------------------------------------------------------
__global__ void split_f32(const float* __restrict__ in, __half* __restrict__ hi,
                          __half* __restrict__ lo, int n4, float scale)
{
    const int stride = gridDim.x * blockDim.x;
    for (int i = blockIdx.x * blockDim.x + threadIdx.x; i < n4; i += stride) {
        float4 v = ((const float4*)in)[i];
        v.x *= scale; v.y *= scale; v.z *= scale; v.w *= scale;
        __half hx = __float2half_rn(v.x), hy = __float2half_rn(v.y);
        __half hz = __float2half_rn(v.z), hw = __float2half_rn(v.w);
        __half lx = __float2half_rn(v.x - __half2float(hx));
        __half ly = __float2half_rn(v.y - __half2float(hy));
        __half lz = __float2half_rn(v.z - __half2float(hz));
        __half lw = __float2half_rn(v.w - __half2float(hw));
        __half2 h01 = __halves2half2(hx, hy), h23 = __halves2half2(hz, hw);
        __half2 l01 = __halves2half2(lx, ly), l23 = __halves2half2(lz, lw);
        uint2 hp, lp;
        hp.x = *(uint32_t*)&h01; hp.y = *(uint32_t*)&h23;
        lp.x = *(uint32_t*)&l01; lp.y = *(uint32_t*)&l23;
        ((uint2*)hi)[i] = hp;
        ((uint2*)lo)[i] = lp;
    }
}

// ---------------------------------------------------------------------------
// HMMA split-3 NT GEMM: C = A . W^T * outscale + bias
// mode 0: write fp16 hi/lo into [b, head, s, d] arrays Chi/Clo
// mode 1: write fp32 row-major into C
// ---------------------------------------------------------------------------
#define TSZ   16384
#define STAGE (4 * TSZ)
#define GSMEM (2 * STAGE)

__global__ __launch_bounds__(256, 1)
void gemm_hmma(const __half* __restrict__ Ahi, const __half* __restrict__ Alo,
               const __half* __restrict__ Bhi, const __half* __restrict__ Blo,
               const float* __restrict__ bias, float* __restrict__ C,
               __half* __restrict__ Chi, __half* __restrict__ Clo,
               int N, int mode, int nheads, float outscale)
{
    extern __shared__ __align__(1024) char sm[];
    const int tid  = threadIdx.x;
    const int wid  = tid >> 5;
    const int lane = tid & 31;
    const int m0 = blockIdx.y * 128;
    const int n0 = blockIdx.x * 128;
    const int wm = (wid >> 2) * 64;
    const int wn = (wid & 3) * 32;
    const uint32_t sbase = smem_u32(sm);

    const __half* Ah = Ahi + (size_t)m0 * KDIM;
    const __half* Al = Alo + (size_t)m0 * KDIM;
    const __half* Bh = Bhi + (size_t)n0 * KDIM;
    const __half* Bl = Blo + (size_t)n0 * KDIM;

    float acc[4][4][4];
#pragma unroll
    for (int i = 0; i < 4; i++)
#pragma unroll
        for (int j = 0; j < 4; j++)
#pragma unroll
            for (int k = 0; k < 4; k++) acc[i][j][k] = 0.0f;

    auto load_stage = [&](int s, int k0) {
        const uint32_t base = sbase + s * STAGE;
#pragma unroll
        for (int i = 0; i < 4; i++) {
            const int idx = tid + i * 256;
            const int r = idx >> 3, c = idx & 7;
            const uint32_t dst = r * 128 + (((uint32_t)(c ^ (r & 7))) << 4);
            const size_t src = (size_t)r * KDIM + k0 + c * 8;
            CP16(base + 0 * TSZ + dst, (const char*)(Ah + src));
            CP16(base + 1 * TSZ + dst, (const char*)(Al + src));
            CP16(base + 2 * TSZ + dst, (const char*)(Bh + src));
            CP16(base + 3 * TSZ + dst, (const char*)(Bl + src));
        }
        CP_COMMIT();
    };

    load_stage(0, 0);

    const int NIT = KDIM / 64;
    for (int it = 0; it < NIT; ++it) {
        if (it + 1 < NIT) load_stage((it + 1) & 1, (it + 1) * 64);
        if (it + 1 < NIT) { CP_WAIT(1); } else { CP_WAIT(0); }
        __syncthreads();

        const uint32_t stg = sbase + (it & 1) * STAGE;
        const uint32_t sAh = stg, sAl = stg + TSZ;
        const uint32_t sBh = stg + 2 * TSZ, sBl = stg + 3 * TSZ;

        uint32_t bh[4][4], bl[4][4];
#pragma unroll
        for (int k16 = 0; k16 < 4; ++k16) {
            if ((k16 & 1) == 0) {
#pragma unroll
                for (int nt = 0; nt < 4; ++nt) {
                    const int r = wn + nt * 8 + (lane & 7);
                    const int c = k16 * 2 + (lane >> 3);
                    const uint32_t off = r * 128 + (((uint32_t)(c ^ (r & 7))) << 4);
                    ldsm4(bh[nt][0], bh[nt][1], bh[nt][2], bh[nt][3], sBh + off);
                    ldsm4(bl[nt][0], bl[nt][1], bl[nt][2], bl[nt][3], sBl + off);
                }
            }
            const int bo = (k16 & 1) * 2;

            uint32_t ah[4][4], al[4][4];
#pragma unroll
            for (int mt = 0; mt < 4; ++mt) {
                const int r = wm + mt * 16 + (lane & 15);
                const int c = k16 * 2 + (lane >> 4);
                const uint32_t off = r * 128 + (((uint32_t)(c ^ (r & 7))) << 4);
                ldsm4(ah[mt][0], ah[mt][1], ah[mt][2], ah[mt][3], sAh + off);
                ldsm4(al[mt][0], al[mt][1], al[mt][2], al[mt][3], sAl + off);
            }
#pragma unroll
            for (int mt = 0; mt < 4; ++mt)
#pragma unroll
                for (int nt = 0; nt < 4; ++nt) {
                    mma16816(acc[mt][nt], ah[mt], bh[nt][bo], bh[nt][bo + 1]);
                    mma16816(acc[mt][nt], ah[mt], bl[nt][bo], bl[nt][bo + 1]);
                    mma16816(acc[mt][nt], al[mt], bh[nt][bo], bh[nt][bo + 1]);
                }
        }
        __syncthreads();
    }

    // ---- epilogue ----
#pragma unroll
    for (int mt = 0; mt < 4; ++mt) {
#pragma unroll
        for (int nt = 0; nt < 4; ++nt) {
            const int o = n0 + wn + nt * 8 + 2 * (lane & 3);
            const float b0 = bias[o], b1 = bias[o + 1];
#pragma unroll
            for (int half = 0; half < 2; ++half) {
                const int t = m0 + wm + mt * 16 + (lane >> 2) + half * 8;
                float vx = acc[mt][nt][half * 2 + 0] * outscale + b0;
                float vy = acc[mt][nt][half * 2 + 1] * outscale + b1;
                if (mode == 0) {
                    const int bb = t >> 11, s = t & 2047;
                    const int hh = o >> 7, d = o & 127;
                    const size_t idx =
                        (((size_t)(bb * nheads + hh)) * SEQL + s) * DHEAD + d;
                    __half hx = __float2half_rn(vx), hy = __float2half_rn(vy);
                    __half lx = __float2half_rn(vx - __half2float(hx));
                    __half ly = __float2half_rn(vy - __half2float(hy));
                    *(__half2*)&Chi[idx] = __halves2half2(hx, hy);
                    *(__half2*)&Clo[idx] = __halves2half2(lx, ly);
                } else {
                    float2 v; v.x = vx; v.y = vy;
                    *(float2*)&C[(size_t)t * N + o] = v;
                }
            }
        }
    }
}

// ---------------------------------------------------------------------------
// HMMA causal flash attention (split-fp16).
// CTA: 128 q rows, 8 warps x 16 rows. KV tiles of 64, double-buffered cp.async.
// smem: Qh|Ql [128][128] fp16 swizzled; 2 stages of {Kh,Kl,Vh,Vl}[64][128].
// Output written as fp16 hi/lo into [t][hid] (o-proj input). No bias.
// ---------------------------------------------------------------------------
#define FA_QT    32768                 // one 128x128 fp16 tile
#define FA_KVT   16384                 // one 64x128 fp16 tile
#define FA_STG   (4 * FA_KVT)          // 65536
#define FA_SMEM  (2 * FA_QT + 2 * FA_STG)   // 196608

__global__ __launch_bounds__(256, 1)
void flash_hmma(const __half* __restrict__ Qh_, const __half* __restrict__ Ql_,
                const __half* __restrict__ Kh_, const __half* __restrict__ Kl_,
                const __half* __restrict__ Vh_, const __half* __restrict__ Vl_,
                __half* __restrict__ Ohi, __half* __restrict__ Olo)
{
    extern __shared__ __align__(1024) char sm[];
    const uint32_t sb  = smem_u32(sm);
    const uint32_t sQh = sb, sQl = sb + FA_QT;
    const uint32_t sKV = sb + 2 * FA_QT;

    const int tid = threadIdx.x, wid = tid >> 5, lane = tid & 31;
    const int qb = gridDim.x - 1 - blockIdx.x;   // heavy tiles first
    const int q0 = qb * 128;
    const int h = blockIdx.y, b = blockIdx.z, kvh = h & 7;
    const int wq = wid * 16;
    const float scale = 0.08838834764831845f;    // 1/sqrt(128)

    const size_t qbase  = (((size_t)(b * NHEAD + h))  * SEQL + q0) * DHEAD;
    const size_t kvbase = (((size_t)(b * NKVH + kvh)) * SEQL) * DHEAD;

    // Q tiles (hi+lo): 2048 16B chunks each
#pragma unroll
    for (int i = 0; i < 8; i++) {
        const int idx = tid + i * 256;
        const int r = idx >> 4, c = idx & 15;
        const uint32_t dst = r * 256 + (((uint32_t)(c ^ (r & 7))) << 4);
        const size_t src = qbase + (size_t)r * DHEAD + c * 8;
        CP16(sQh + dst, (const char*)(Qh_ + src));
        CP16(sQl + dst, (const char*)(Ql_ + src));
    }
    auto load_kv = [&](int j, int s) {
        const uint32_t st = sKV + s * FA_STG;
        const size_t base = kvbase + (size_t)j * 64 * DHEAD;
#pragma unroll
        for (int i = 0; i < 4; i++) {
            const int idx = tid + i * 256;
            const int r = idx >> 4, c = idx & 15;
            const uint32_t dst = r * 256 + (((uint32_t)(c ^ (r & 7))) << 4);
            const size_t src = base + (size_t)r * DHEAD + c * 8;
            CP16(st + 0 * FA_KVT + dst, (const char*)(Kh_ + src));
            CP16(st + 1 * FA_KVT + dst, (const char*)(Kl_ + src));
            CP16(st + 2 * FA_KVT + dst, (const char*)(Vh_ + src));
            CP16(st + 3 * FA_KVT + dst, (const char*)(Vl_ + src));
        }
    };
    load_kv(0, 0);
    CP_COMMIT();

    float O[16][4];
#pragma unroll
    for (int i = 0; i < 16; i++)
#pragma unroll
        for (int k = 0; k < 4; k++) O[i][k] = 0.0f;
    float m0 = -1e30f, m1 = -1e30f, l0 = 0.0f, l1 = 0.0f;

    const int njt = (q0 + 128) / 64;
    for (int j = 0; j < njt; j++) {
        if (j + 1 < njt) { load_kv(j + 1, (j + 1) & 1); CP_COMMIT(); CP_WAIT(1); }
        else             { CP_WAIT(0); }
        __syncthreads();
        const uint32_t st = sKV + (j & 1) * FA_STG;
        const int j0 = j * 64;

        if (q0 + wq + 15 >= j0) {       // warp has unmasked rows in this tile
            // ---- S = Q K^T (split-3) ----
            float S[8][4];
#pragma unroll
            for (int nt = 0; nt < 8; nt++)
#pragma unroll
                for (int k = 0; k < 4; k++) S[nt][k] = 0.0f;

#pragma unroll
            for (int kp = 0; kp < 4; kp++) {
                uint32_t ah[2][4], al[2][4];
#pragma unroll
                for (int x = 0; x < 2; x++) {
                    const int ks = kp * 2 + x;
                    const int r = wq + (lane & 15);
                    const int c = ks * 2 + (lane >> 4);
                    const uint32_t off = r * 256 + (((uint32_t)(c ^ (r & 7))) << 4);
                    ldsm4(ah[x][0], ah[x][1], ah[x][2], ah[x][3], sQh + off);
                    ldsm4(al[x][0], al[x][1], al[x][2], al[x][3], sQl + off);
                }
#pragma unroll
                for (int nt = 0; nt < 8; nt++) {
                    const int r = nt * 8 + (lane & 7);
                    const int c = kp * 4 + (lane >> 3);
                    const uint32_t off = r * 256 + (((uint32_t)(c ^ (r & 7))) << 4);
                    uint32_t kh[4], kl[4];
                    ldsm4(kh[0], kh[1], kh[2], kh[3], st + 0 * FA_KVT + off);
                    ldsm4(kl[0], kl[1], kl[2], kl[3], st + 1 * FA_KVT + off);
                    mma16816(S[nt], ah[0], kh[0], kh[1]);
                    mma16816(S[nt], ah[0], kl[0], kl[1]);
                    mma16816(S[nt], al[0], kh[0], kh[1]);
                    mma16816(S[nt], ah[1], kh[2], kh[3]);
                    mma16816(S[nt], ah[1], kl[2], kl[3]);
                    mma16816(S[nt], al[1], kh[2], kh[3]);
                }
            }

            // ---- causal mask ----
            if (j0 + 63 > q0 + wq) {
                const int row0 = q0 + wq + (lane >> 2), row1 = row0 + 8;
#pragma unroll
                for (int nt = 0; nt < 8; nt++) {
                    const int cb = j0 + nt * 8 + 2 * (lane & 3);
                    if (cb     > row0) S[nt][0] = -1e30f;
                    if (cb + 1 > row0) S[nt][1] = -1e30f;
                    if (cb     > row1) S[nt][2] = -1e30f;
                    if (cb + 1 > row1) S[nt][3] = -1e30f;
                }
            }

            // ---- online softmax ----
            float tm0 = -1e30f, tm1 = -1e30f;
#pragma unroll
            for (int nt = 0; nt < 8; nt++) {
                tm0 = fmaxf(tm0, fmaxf(S[nt][0], S[nt][1]));
                tm1 = fmaxf(tm1, fmaxf(S[nt][2], S[nt][3]));
            }
            tm0 = fmaxf(tm0, __shfl_xor_sync(0xffffffffu, tm0, 1));
            tm0 = fmaxf(tm0, __shfl_xor_sync(0xffffffffu, tm0, 2));
            tm1 = fmaxf(tm1, __shfl_xor_sync(0xffffffffu, tm1, 1));
            tm1 = fmaxf(tm1, __shfl_xor_sync(0xffffffffu, tm1, 2));
            const float mn0 = fmaxf(m0, tm0), mn1 = fmaxf(m1, tm1);
            const float cr0 = __expf((m0 - mn0) * scale);
            const float cr1 = __expf((m1 - mn1) * scale);
            m0 = mn0; m1 = mn1;

            uint32_t ph[8][2], pl[8][2];
            float ps0 = 0.0f, ps1 = 0.0f;
#pragma unroll
            for (int nt = 0; nt < 8; nt++) {
                const float p0 = __expf((S[nt][0] - mn0) * scale);
                const float p1 = __expf((S[nt][1] - mn0) * scale);
                const float p2 = __expf((S[nt][2] - mn1) * scale);
                const float p3 = __expf((S[nt][3] - mn1) * scale);
                ps0 += p0 + p1;  ps1 += p2 + p3;
                const __half h0 = __float2half_rn(p0), h1 = __float2half_rn(p1);
                const __half h2 = __float2half_rn(p2), h3 = __float2half_rn(p3);
                const __half e0 = __float2half_rn(p0 - __half2float(h0));
                const __half e1 = __float2half_rn(p1 - __half2float(h1));
                const __half e2 = __float2half_rn(p2 - __half2float(h2));
                const __half e3 = __float2half_rn(p3 - __half2float(h3));
                __half2 a01 = __halves2half2(h0, h1), a23 = __halves2half2(h2, h3);
                __half2 b01 = __halves2half2(e0, e1), b23 = __halves2half2(e2, e3);
                ph[nt][0] = *(uint32_t*)&a01;  ph[nt][1] = *(uint32_t*)&a23;
                pl[nt][0] = *(uint32_t*)&b01;  pl[nt][1] = *(uint32_t*)&b23;
            }
            ps0 += __shfl_xor_sync(0xffffffffu, ps0, 1);
            ps0 += __shfl_xor_sync(0xffffffffu, ps0, 2);
            ps1 += __shfl_xor_sync(0xffffffffu, ps1, 1);
            ps1 += __shfl_xor_sync(0xffffffffu, ps1, 2);
            l0 = l0 * cr0 + ps0;
            l1 = l1 * cr1 + ps1;
#pragma unroll
            for (int nt = 0; nt < 16; nt++) {
                O[nt][0] *= cr0; O[nt][1] *= cr0;
                O[nt][2] *= cr1; O[nt][3] *= cr1;
            }

            // ---- O += P V (split-3) ----
#pragma unroll
            for (int kt = 0; kt < 4; kt++) {
                uint32_t pah[4], pal[4];
                pah[0] = ph[2 * kt][0];     pah[1] = ph[2 * kt][1];
                pah[2] = ph[2 * kt + 1][0]; pah[3] = ph[2 * kt + 1][1];
                pal[0] = pl[2 * kt][0];     pal[1] = pl[2 * kt][1];
                pal[2] = pl[2 * kt + 1][0]; pal[3] = pl[2 * kt + 1][1];
#pragma unroll
                for (int np = 0; np < 8; np++) {
                    const int r = kt * 16 + (lane & 15);
                    const int c = np * 2 + (lane >> 4);
                    const uint32_t off = r * 256 + (((uint32_t)(c ^ (r & 7))) << 4);
                    uint32_t vh[4], vl[4];
                    ldsm4t(vh[0], vh[1], vh[2], vh[3], st + 2 * FA_KVT + off);
                    ldsm4t(vl[0], vl[1], vl[2], vl[3], st + 3 * FA_KVT + off);
                    mma16816(O[2 * np],     pah, vh[0], vh[1]);
                    mma16816(O[2 * np],     pah, vl[0], vl[1]);
                    mma16816(O[2 * np],     pal, vh[0], vh[1]);
                    mma16816(O[2 * np + 1], pah, vh[2], vh[3]);
                    mma16816(O[2 * np + 1], pah, vl[2], vl[3]);
                    mma16816(O[2 * np + 1], pal, vh[2], vh[3]);
                }
            }
        }
        __syncthreads();
    }

    // ---- normalize + write split output [t][hid] ----
    const float i0 = 1.0f / l0, i1 = 1.0f / l1;
    const int t0 = b * SEQL + q0 + wq + (lane >> 2);
#pragma unroll
    for (int nt = 0; nt < 16; nt++) {
        const int col = h * DHEAD + nt * 8 + 2 * (lane & 3);
        const float y0 = O[nt][0] * i0, y1 = O[nt][1] * i0;
        const float y2 = O[nt][2] * i1, y3 = O[nt][3] * i1;
        const __half h0 = __float2half_rn(y0), h1 = __float2half_rn(y1);
        const __half h2 = __float2half_rn(y2), h3 = __float2half_rn(y3);
        const __half e0 = __float2half_rn(y0 - __half2float(h0));
        const __half e1 = __float2half_rn(y1 - __half2float(h1));
        const __half e2 = __float2half_rn(y2 - __half2float(h2));
        const __half e3 = __float2half_rn(y3 - __half2float(h3));
        __half2 a01 = __halves2half2(h0, h1), a23 = __halves2half2(h2, h3);
        __half2 b01 = __halves2half2(e0, e1), b23 = __halves2half2(e2, e3);
        *(__half2*)&Ohi[(size_t)t0 * KDIM + col]       = a01;
        *(__half2*)&Olo[(size_t)t0 * KDIM + col]       = b01;
        *(__half2*)&Ohi[(size_t)(t0 + 8) * KDIM + col] = a23;
        *(__half2*)&Olo[(size_t)(t0 + 8) * KDIM + col] = b23;
    }
}

// ---------------------------------------------------------------------------
extern "C" void kernel_launch(void* const* d_in, const int* in_sizes, int n_in,
                              void* d_out, int out_size)
{
    const float* x   = (const float*)d_in[0];
    // d_in[1] = mask: causal structure applied analytically, not read.
    const float* q_w = (const float*)d_in[2];
    const float* q_b = (const float*)d_in[3];
    const float* k_w = (const float*)d_in[4];
    const float* k_b = (const float*)d_in[5];
    const float* v_w = (const float*)d_in[6];
    const float* v_b = (const float*)d_in[7];
    const float* o_w = (const float*)d_in[8];
    const float* o_b = (const float*)d_in[9];
    float* out = (float*)d_out;

    __half *xh, *xl, *wqh, *wql, *wkh, *wkl, *wvh, *wvl, *woh, *wol;
    __half *qh, *ql, *kh, *kl, *vh, *vl, *ah, *al;
    cudaGetSymbolAddress((void**)&xh, g_Xhi);   cudaGetSymbolAddress((void**)&xl, g_Xlo);
    cudaGetSymbolAddress((void**)&wqh, g_Wqh);  cudaGetSymbolAddress((void**)&wql, g_Wql);
    cudaGetSymbolAddress((void**)&wkh, g_Wkh);  cudaGetSymbolAddress((void**)&wkl, g_Wkl);
    cudaGetSymbolAddress((void**)&wvh, g_Wvh);  cudaGetSymbolAddress((void**)&wvl, g_Wvl);
    cudaGetSymbolAddress((void**)&woh, g_Woh);  cudaGetSymbolAddress((void**)&wol, g_Wol);
    cudaGetSymbolAddress((void**)&qh, g_Qh);    cudaGetSymbolAddress((void**)&ql, g_Ql);
    cudaGetSymbolAddress((void**)&kh, g_Kh2);   cudaGetSymbolAddress((void**)&kl, g_Kl2);
    cudaGetSymbolAddress((void**)&vh, g_Vh2);   cudaGetSymbolAddress((void**)&vl, g_Vl2);
    cudaGetSymbolAddress((void**)&ah, g_Ahi);   cudaGetSymbolAddress((void**)&al, g_Alo);

    cudaFuncSetAttribute(gemm_hmma, cudaFuncAttributeMaxDynamicSharedMemorySize,
                         GSMEM);
    cudaFuncSetAttribute(flash_hmma, cudaFuncAttributeMaxDynamicSharedMemorySize,
                         FA_SMEM);

    const float WS = 1024.0f, IWS = 1.0f / 1024.0f;
    dim3 blk(256);

    // Split inputs + weights into fp16 hi/lo
    split_f32<<<1024, 256>>>(x,   xh,  xl,  (NTOK * KDIM) / 4,         1.0f);
    split_f32<<<1024, 256>>>(q_w, wqh, wql, (HIDN * KDIM) / 4,         WS);
    split_f32<<<512,  256>>>(k_w, wkh, wkl, (NKVH * DHEAD * KDIM) / 4, WS);
    split_f32<<<512,  256>>>(v_w, wvh, wvl, (NKVH * DHEAD * KDIM) / 4, WS);
    split_f32<<<1024, 256>>>(o_w, woh, wol, (HIDN * KDIM) / 4,         WS);

    // Projections -> fp16 hi/lo QKV in [b, head, s, d]
    gemm_hmma<<<dim3(32, 32), blk, GSMEM>>>(xh, xl, wqh, wql, q_b, nullptr,
                                            qh, ql, HIDN, 0, NHEAD, IWS);
    gemm_hmma<<<dim3(8, 32),  blk, GSMEM>>>(xh, xl, wkh, wkl, k_b, nullptr,
                                            kh, kl, NKVH * DHEAD, 0, NKVH, IWS);
    gemm_hmma<<<dim3(8, 32),  blk, GSMEM>>>(xh, xl, wvh, wvl, v_b, nullptr,
                                            vh, vl, NKVH * DHEAD, 0, NKVH, IWS);

    // Attention (HMMA split-fp16), writes o-proj input directly
    flash_hmma<<<dim3(SEQL / 128, NHEAD, NBATCH), blk, FA_SMEM>>>(
        qh, ql, kh, kl, vh, vl, ah, al);

    // Output projection (fp32 out)
    gemm_hmma<<<dim3(32, 32), blk, GSMEM>>>(ah, al, woh, wol, o_b, out,
                                            nullptr, nullptr, HIDN, 1, 0, IWS);
}